// round 6
// baseline (speedup 1.0000x reference)
#include <cuda_runtime.h>
#include <cstdint>

typedef unsigned int u32;

#define NJ        33
#define FD        64
#define B_TOTAL   32768
#define M_TOTAL   (B_TOTAL*NJ)        // 1081344
#define TILE_M    128
#define NTILES    (M_TOTAL/TILE_M)    // 8448
#define GRID_MAIN 148
#define NTHREADS  256

#define A_STRIDE  68                  // floats per row (272B: 8 rows -> 8 distinct 16B offsets)
#define AH_F      (TILE_M*A_STRIDE)   // floats per A (or H) tile = 8704
#define AH_BYTES  (AH_F*4)            // 34816

// smem layout (float indices)
#define F_B       0                   // packed B fragments: 24576 floats (96KB)
#define F_A       24576               // A (agg) then H: 2*AH_F
#define F_BIAS    (F_A + 2*AH_F)      // 41984
#define SMEM_FLOATS (F_BIAS + 256)
#define SMEM_BYTES  (SMEM_FLOATS*4)   // 168960

// ---------------- neighbor tables (self first) ----------------
__constant__ int c_nbr[NJ][4] = {
    {0,0,0,0},{1,0,0,0},{2,0,0,0},{3,0,0,0},{4,0,0,0},{5,0,0,0},{6,0,0,0},
    {7,0,0,0},{8,0,0,0},{9,0,0,0},{10,0,0,0},
    {11,12,23,13},{12,11,24,14},{13,11,15,0},{14,12,16,0},{15,13,0,0},{16,14,0,0},
    {17,0,0,0},{18,0,0,0},{19,0,0,0},{20,0,0,0},{21,0,0,0},{22,0,0,0},
    {23,11,24,25},{24,12,23,26},{25,23,27,0},{26,24,28,0},{27,25,0,0},{28,26,0,0},
    {29,0,0,0},{30,0,0,0},{31,0,0,0},{32,0,0,0}
};
__constant__ int c_cnt[NJ] = {1,1,1,1,1,1,1,1,1,1,1, 4,4,3,3,2,2, 1,1,1,1,1,1,
                              4,4,3,3,2,2, 1,1,1,1};
__constant__ float c_invcnt[NJ] = {1.f,1.f,1.f,1.f,1.f,1.f,1.f,1.f,1.f,1.f,1.f,
                                   0.25f,0.25f,1.f/3.f,1.f/3.f,0.5f,0.5f,
                                   1.f,1.f,1.f,1.f,1.f,1.f,
                                   0.25f,0.25f,1.f/3.f,1.f/3.f,0.5f,0.5f,
                                   1.f,1.f,1.f,1.f};

// packed B fragments: float4 per (ks 0..7, ds 0..1, blk 0..11, lane 0..31)
//  gate = blk>>2 (0=r,1=z,2=n); n = gate*64 + ds*32 + (blk&3)*8 + (lane>>2)
//  k0 = ks*8 + (lane&3), k1 = k0+4
//  .x=GA[n][k0] .y=GA[n][k1] .z=GH[n][k0] .w=GH[n][k1]
__device__ __align__(16) float g_Bpack[8*2*12*32*4];   // 24576 floats
__device__ float g_bias[256];                          // R | Z | IN | HN

// ---------------- helpers ----------------
__device__ __forceinline__ u32 smem_u32(const void* p) {
    u32 a;
    asm("{ .reg .u64 t; cvta.to.shared.u64 t, %1; cvt.u32.u64 %0, t; }" : "=r"(a) : "l"(p));
    return a;
}
__device__ __forceinline__ float tf32r(float x) {
    u32 u; asm("cvt.rna.tf32.f32 %0, %1;" : "=r"(u) : "f"(x));
    return __uint_as_float(u);
}
__device__ __forceinline__ float4 tf4(float4 v) {
    return make_float4(tf32r(v.x), tf32r(v.y), tf32r(v.z), tf32r(v.w));
}
__device__ __forceinline__ float tanh_ap(float x) {
    float y; asm("tanh.approx.f32 %0, %1;" : "=f"(y) : "f"(x)); return y;
}
__device__ __forceinline__ float sigm(float x) { return 0.5f * tanh_ap(0.5f * x) + 0.5f; }
__device__ __forceinline__ void mma8(float c[4], const u32 a[4], u32 b0, u32 b1) {
    asm volatile("mma.sync.aligned.m16n8k8.row.col.f32.tf32.tf32.f32 "
                 "{%0,%1,%2,%3}, {%4,%5,%6,%7}, {%8,%9}, {%0,%1,%2,%3};"
                 : "+f"(c[0]), "+f"(c[1]), "+f"(c[2]), "+f"(c[3])
                 : "r"(a[0]), "r"(a[1]), "r"(a[2]), "r"(a[3]), "r"(b0), "r"(b1));
}
__device__ __forceinline__ void ldsm4(u32 r[4], u32 addr) {
    asm volatile("ldmatrix.sync.aligned.m8n8.x4.shared.b16 {%0,%1,%2,%3}, [%4];"
                 : "=r"(r[0]), "=r"(r[1]), "=r"(r[2]), "=r"(r[3]) : "r"(addr));
}
__device__ __forceinline__ void pf_l2(const void* p) {
    asm volatile("prefetch.global.L2 [%0];" :: "l"(p));
}

// ---------------- prep: fold linear chain, pack fragments, tf32-round ----------------
__global__ void prep_kernel(const float* __restrict__ msg_w, const float* __restrict__ msg_b,
                            const float* __restrict__ w_ih, const float* __restrict__ w_hh,
                            const float* __restrict__ b_ih, const float* __restrict__ b_hh) {
    int t = blockIdx.x * blockDim.x + threadIdx.x;
    if (t < 8*2*12*32) {
        int lane = t & 31;
        int blk  = (t >> 5) % 12;
        int ds   = (t >> 5) / 12 % 2;
        int ks   = t / (2*12*32);
        int g = lane >> 2, tig = lane & 3;
        int gate = blk >> 2;
        int n = gate*64 + ds*32 + (blk & 3)*8 + g;
        int k0 = ks*8 + tig, k1 = k0 + 4;
        float ga0 = 0.f, ga1 = 0.f;
        #pragma unroll 8
        for (int f = 0; f < FD; f++) {
            float wi = w_ih[n*FD + f];
            ga0 += msg_w[f*FD + k0] * wi;
            ga1 += msg_w[f*FD + k1] * wi;
        }
        ((float4*)g_Bpack)[t] = make_float4(tf32r(ga0), tf32r(ga1),
                                            tf32r(w_hh[n*FD + k0]), tf32r(w_hh[n*FD + k1]));
    }
    if (t < 192) {
        float s = 0.f;
        #pragma unroll 8
        for (int f = 0; f < FD; f++) s += msg_b[f] * w_ih[t*FD + f];
        float bA = s + b_ih[t];
        if (t < 128)      g_bias[t] = bA + b_hh[t];
        else            { g_bias[t] = bA; g_bias[t + 64] = b_hh[t]; }
    }
}

// ---------------- main persistent kernel ----------------
__global__ void __launch_bounds__(NTHREADS, 1)
skeleton_gnn_m128(const float* __restrict__ feats,
                  const float* __restrict__ vis,
                  float* __restrict__ out)
{
    extern __shared__ float sm[];
    const int tid = threadIdx.x;

    // stage packed weights + biases
    {
        const float4* gb = (const float4*)g_Bpack;
        float4* s4 = (float4*)(sm + F_B);
        #pragma unroll
        for (int i = 0; i < 24; i++) s4[tid + i*NTHREADS] = gb[tid + i*NTHREADS];
        sm[F_BIAS + tid] = g_bias[tid];
    }
    __syncthreads();

    const int w    = tid >> 5;
    const int lane = tid & 31;
    const int g    = lane >> 2;
    const int tig  = lane & 3;
    const int wm   = w & 3;             // m32 block within tile
    const int ds   = w >> 2;            // d-slice
    const int rb   = wm * 32;

    // ldmatrix per-lane byte offsets within A region (per mb)
    const int mat  = lane >> 3;
    const int arow = (lane & 7) + ((mat & 1) << 3);
    const u32 sabase = smem_u32(sm + F_A);
    const u32 aoff0 = sabase + (u32)((((rb + arow)*A_STRIDE) + ((mat >> 1) << 2)) * 4);
    const u32 aoff1 = aoff0 + (u32)(16*A_STRIDE*4);

    // hoist biases into registers
    float bR[4][2], bZ[4][2], bI[4][2], bH[4][2];
    {
        const float* sbias = sm + F_BIAS;
        #pragma unroll
        for (int blk = 0; blk < 4; blk++) {
            int col = ds*32 + blk*8 + 2*tig;
            bR[blk][0] = sbias[col];       bR[blk][1] = sbias[col+1];
            bZ[blk][0] = sbias[64+col];    bZ[blk][1] = sbias[64+col+1];
            bI[blk][0] = sbias[128+col];   bI[blk][1] = sbias[128+col+1];
            bH[blk][0] = sbias[192+col];   bH[blk][1] = sbias[192+col+1];
        }
    }
    const float4* Bp4 = (const float4*)(sm + F_B);

    // gather indices (one half-row per thread)
    const int grow = tid >> 1;          // 0..127
    const int kc4  = (tid & 1) * 8;     // float4 offset in row

    int iter = 0;
    for (int t = blockIdx.x; t < NTILES; t += GRID_MAIN, ++iter) {
        const int gr0 = t * TILE_M;

        // ---- protect A/H from overwrite until all warps finished reading ----
        if (iter > 0) __syncthreads();

        // ======== phase 1: gather agg + h into smem (tf32-rounded) ========
        {
            float* As = sm + F_A;
            float* Ah = As + AH_F;
            int gr = gr0 + grow;
            int b = (int)((u32)gr / 33u);
            int j = gr - b*33;
            const float4* fb = (const float4*)feats + (size_t)b * 528;   // 33*16
            const float4* srow = fb + j*16 + kc4;
            float4 s0 = srow[0], s1 = srow[1], s2 = srow[2], s3 = srow[3];
            float4 s4v = srow[4], s5 = srow[5], s6 = srow[6], s7 = srow[7];
            float* hp = Ah + grow*A_STRIDE + kc4*4;
            *(float4*)(hp+0)  = tf4(s0);  *(float4*)(hp+4)  = tf4(s1);
            *(float4*)(hp+8)  = tf4(s2);  *(float4*)(hp+12) = tf4(s3);
            *(float4*)(hp+16) = tf4(s4v); *(float4*)(hp+20) = tf4(s5);
            *(float4*)(hp+24) = tf4(s6);  *(float4*)(hp+28) = tf4(s7);

            float w0 = __ldg(vis + b*NJ + j);
            float a[32];
            a[0]=w0*s0.x; a[1]=w0*s0.y; a[2]=w0*s0.z; a[3]=w0*s0.w;
            a[4]=w0*s1.x; a[5]=w0*s1.y; a[6]=w0*s1.z; a[7]=w0*s1.w;
            a[8]=w0*s2.x; a[9]=w0*s2.y; a[10]=w0*s2.z; a[11]=w0*s2.w;
            a[12]=w0*s3.x; a[13]=w0*s3.y; a[14]=w0*s3.z; a[15]=w0*s3.w;
            a[16]=w0*s4v.x; a[17]=w0*s4v.y; a[18]=w0*s4v.z; a[19]=w0*s4v.w;
            a[20]=w0*s5.x; a[21]=w0*s5.y; a[22]=w0*s5.z; a[23]=w0*s5.w;
            a[24]=w0*s6.x; a[25]=w0*s6.y; a[26]=w0*s6.z; a[27]=w0*s6.w;
            a[28]=w0*s7.x; a[29]=w0*s7.y; a[30]=w0*s7.z; a[31]=w0*s7.w;

            int cnt = c_cnt[j];
            #pragma unroll
            for (int qi = 1; qi < 4; ++qi) {
                if (qi < cnt) {
                    int nb = c_nbr[j][qi];
                    float wv = __ldg(vis + b*NJ + nb);
                    const float4* nr = fb + nb*16 + kc4;
                    #pragma unroll
                    for (int i4 = 0; i4 < 8; i4++) {
                        float4 nv = nr[i4];
                        a[i4*4+0] += wv*nv.x; a[i4*4+1] += wv*nv.y;
                        a[i4*4+2] += wv*nv.z; a[i4*4+3] += wv*nv.w;
                    }
                }
            }
            float ic = c_invcnt[j];
            float* ap = As + grow*A_STRIDE + kc4*4;
            #pragma unroll
            for (int i4 = 0; i4 < 8; i4++) {
                float4 v = make_float4(a[i4*4]*ic, a[i4*4+1]*ic, a[i4*4+2]*ic, a[i4*4+3]*ic);
                *(float4*)(ap + i4*4) = tf4(v);
            }
        }
        __syncthreads();

        // ---- L2 prefetch for next tile (overlaps with MMA below) ----
        {
            int tn = t + GRID_MAIN;
            if (tn < NTILES) {
                const char* base = (const char*)feats + (size_t)tn * TILE_M * 256;
                pf_l2(base + grow*256 + (tid & 1)*128);
                if (tid < 6) {
                    int b0n = (tn*TILE_M) / 33;
                    pf_l2(vis + b0n*NJ + tid*32);
                }
            }
        }

        // ======== phase 2: MMA (2 m16 blocks share each B fragment) ========
        float accR[2][4][4], accZ[2][4][4], accI[2][4][4], accH[2][4][4];
        #pragma unroll
        for (int mb = 0; mb < 2; mb++)
            #pragma unroll
            for (int blk = 0; blk < 4; blk++) {
                accR[mb][blk][0]=bR[blk][0]; accR[mb][blk][1]=bR[blk][1];
                accR[mb][blk][2]=bR[blk][0]; accR[mb][blk][3]=bR[blk][1];
                accZ[mb][blk][0]=bZ[blk][0]; accZ[mb][blk][1]=bZ[blk][1];
                accZ[mb][blk][2]=bZ[blk][0]; accZ[mb][blk][3]=bZ[blk][1];
                accI[mb][blk][0]=bI[blk][0]; accI[mb][blk][1]=bI[blk][1];
                accI[mb][blk][2]=bI[blk][0]; accI[mb][blk][3]=bI[blk][1];
                accH[mb][blk][0]=bH[blk][0]; accH[mb][blk][1]=bH[blk][1];
                accH[mb][blk][2]=bH[blk][0]; accH[mb][blk][3]=bH[blk][1];
            }

        #pragma unroll
        for (int ks = 0; ks < 8; ks++) {
            u32 fa0[4], fh0[4], fa1[4], fh1[4];
            ldsm4(fa0, aoff0 + (u32)(ks*32));
            ldsm4(fh0, aoff0 + (u32)(ks*32) + AH_BYTES);
            ldsm4(fa1, aoff1 + (u32)(ks*32));
            ldsm4(fh1, aoff1 + (u32)(ks*32) + AH_BYTES);
            const float4* bp = Bp4 + ((ks*2 + ds)*12)*32 + lane;
            #pragma unroll
            for (int blk = 0; blk < 4; blk++) {
                float4 bw = bp[blk*32];
                u32 x = __float_as_uint(bw.x), y = __float_as_uint(bw.y);
                u32 zc = __float_as_uint(bw.z), wc = __float_as_uint(bw.w);
                mma8(accR[0][blk], fa0, x, y);
                mma8(accR[0][blk], fh0, zc, wc);
                mma8(accR[1][blk], fa1, x, y);
                mma8(accR[1][blk], fh1, zc, wc);
            }
            #pragma unroll
            for (int blk = 0; blk < 4; blk++) {
                float4 bw = bp[(4+blk)*32];
                u32 x = __float_as_uint(bw.x), y = __float_as_uint(bw.y);
                u32 zc = __float_as_uint(bw.z), wc = __float_as_uint(bw.w);
                mma8(accZ[0][blk], fa0, x, y);
                mma8(accZ[0][blk], fh0, zc, wc);
                mma8(accZ[1][blk], fa1, x, y);
                mma8(accZ[1][blk], fh1, zc, wc);
            }
            #pragma unroll
            for (int blk = 0; blk < 4; blk++) {
                float4 bw = bp[(8+blk)*32];
                u32 x = __float_as_uint(bw.x), y = __float_as_uint(bw.y);
                u32 zc = __float_as_uint(bw.z), wc = __float_as_uint(bw.w);
                mma8(accI[0][blk], fa0, x, y);
                mma8(accH[0][blk], fh0, zc, wc);
                mma8(accI[1][blk], fa1, x, y);
                mma8(accH[1][blk], fh1, zc, wc);
            }
        }

        // ======== phase 3: gates + direct store ========
        #pragma unroll
        for (int mb = 0; mb < 2; mb++) {
            const int r0 = gr0 + rb + mb*16 + g;
            const int r1 = r0 + 8;
            #pragma unroll
            for (int blk = 0; blk < 4; blk++) {
                int d0 = ds*32 + blk*8 + 2*tig;
                float2 h0 = *(const float2*)(feats + (size_t)r0*FD + d0);
                float2 h1 = *(const float2*)(feats + (size_t)r1*FD + d0);
                float2 o0, o1;
                {
                    float r = sigm(accR[mb][blk][0]), z = sigm(accZ[mb][blk][0]);
                    float n = tanh_ap(accI[mb][blk][0] + r*accH[mb][blk][0]);
                    o0.x = (1.0f - z)*n + z*h0.x;
                }
                {
                    float r = sigm(accR[mb][blk][1]), z = sigm(accZ[mb][blk][1]);
                    float n = tanh_ap(accI[mb][blk][1] + r*accH[mb][blk][1]);
                    o0.y = (1.0f - z)*n + z*h0.y;
                }
                {
                    float r = sigm(accR[mb][blk][2]), z = sigm(accZ[mb][blk][2]);
                    float n = tanh_ap(accI[mb][blk][2] + r*accH[mb][blk][2]);
                    o1.x = (1.0f - z)*n + z*h1.x;
                }
                {
                    float r = sigm(accR[mb][blk][3]), z = sigm(accZ[mb][blk][3]);
                    float n = tanh_ap(accI[mb][blk][3] + r*accH[mb][blk][3]);
                    o1.y = (1.0f - z)*n + z*h1.y;
                }
                *(float2*)(out + (size_t)r0*FD + d0) = o0;
                *(float2*)(out + (size_t)r1*FD + d0) = o1;
            }
        }
    }
}

extern "C" void kernel_launch(void* const* d_in, const int* in_sizes, int n_in,
                              void* d_out, int out_size)
{
    const float* feats = (const float*)d_in[0];
    const float* vis   = (const float*)d_in[1];
    const float* msg_w = (const float*)d_in[2];
    const float* msg_b = (const float*)d_in[3];
    const float* w_ih  = (const float*)d_in[4];
    const float* w_hh  = (const float*)d_in[5];
    const float* b_ih  = (const float*)d_in[6];
    const float* b_hh  = (const float*)d_in[7];
    float* out = (float*)d_out;

    cudaFuncSetAttribute(skeleton_gnn_m128,
                         cudaFuncAttributeMaxDynamicSharedMemorySize, SMEM_BYTES);

    prep_kernel<<<24, 256>>>(msg_w, msg_b, w_ih, w_hh, b_ih, b_hh);
    skeleton_gnn_m128<<<GRID_MAIN, NTHREADS, SMEM_BYTES>>>(feats, vis, out);
}

// round 7
// speedup vs baseline: 1.1932x; 1.1932x over previous
#include <cuda_runtime.h>
#include <cstdint>

typedef unsigned int u32;

#define NJ        33
#define FD        64
#define B_TOTAL   32768
#define M_TOTAL   (B_TOTAL*NJ)        // 1081344
#define TILE_M    64
#define NTILES    (M_TOTAL/TILE_M)    // 16896
#define GRID_MAIN 148
#define NTHREADS  320                 // 8 consumer warps + 2 producer warps

#define A_STRIDE  68                  // floats/row: 8 rows -> 8 distinct 16B banks groups
#define AH_F      (TILE_M*A_STRIDE)   // 4352 floats per (agg or h) tile
#define AH_BYTES  (AH_F*4)            // 17408
#define BUF_F     (2*AH_F)            // agg + h per buffer = 8704 floats
#define SMEM_BYTES (2*BUF_F*4)        // 69632 (double buffered)

// ---------------- neighbor tables (self first) ----------------
__constant__ int c_nbr[NJ][4] = {
    {0,0,0,0},{1,0,0,0},{2,0,0,0},{3,0,0,0},{4,0,0,0},{5,0,0,0},{6,0,0,0},
    {7,0,0,0},{8,0,0,0},{9,0,0,0},{10,0,0,0},
    {11,12,23,13},{12,11,24,14},{13,11,15,0},{14,12,16,0},{15,13,0,0},{16,14,0,0},
    {17,0,0,0},{18,0,0,0},{19,0,0,0},{20,0,0,0},{21,0,0,0},{22,0,0,0},
    {23,11,24,25},{24,12,23,26},{25,23,27,0},{26,24,28,0},{27,25,0,0},{28,26,0,0},
    {29,0,0,0},{30,0,0,0},{31,0,0,0},{32,0,0,0}
};
__constant__ int c_cnt[NJ] = {1,1,1,1,1,1,1,1,1,1,1, 4,4,3,3,2,2, 1,1,1,1,1,1,
                              4,4,3,3,2,2, 1,1,1,1};
__constant__ float c_invcnt[NJ] = {1.f,1.f,1.f,1.f,1.f,1.f,1.f,1.f,1.f,1.f,1.f,
                                   0.25f,0.25f,1.f/3.f,1.f/3.f,0.5f,0.5f,
                                   1.f,1.f,1.f,1.f,1.f,1.f,
                                   0.25f,0.25f,1.f/3.f,1.f/3.f,0.5f,0.5f,
                                   1.f,1.f,1.f,1.f};

// register-resident weights, written by prep kernel.
// g_W[((wd*8 + ks)*6 + slot)*64 + lane*2 + r]
//   wd = consumer warp (d-slice, n = gatebase + wd*8 + (lane>>2))
//   slot: 0=R/GA 1=R/GH 2=Z/GA 3=Z/GH 4=I/GA 5=HN/GH
//   k = ks*8 + (lane&3) + r*4
__device__ __align__(16) float g_W[8*8*6*64];   // 24576 floats
__device__ float g_bias[256];                   // R | Z | IN | HN

// ---------------- helpers ----------------
__device__ __forceinline__ u32 smem_u32(const void* p) {
    u32 a;
    asm("{ .reg .u64 t; cvta.to.shared.u64 t, %1; cvt.u32.u64 %0, t; }" : "=r"(a) : "l"(p));
    return a;
}
__device__ __forceinline__ float tf32r(float x) {
    u32 u; asm("cvt.rna.tf32.f32 %0, %1;" : "=r"(u) : "f"(x));
    return __uint_as_float(u);
}
__device__ __forceinline__ float4 tf4(float4 v) {
    return make_float4(tf32r(v.x), tf32r(v.y), tf32r(v.z), tf32r(v.w));
}
__device__ __forceinline__ float tanh_ap(float x) {
    float y; asm("tanh.approx.f32 %0, %1;" : "=f"(y) : "f"(x)); return y;
}
__device__ __forceinline__ float sigm(float x) { return 0.5f * tanh_ap(0.5f * x) + 0.5f; }
__device__ __forceinline__ void mma8(float c[4], const u32 a[4], u32 b0, u32 b1) {
    asm volatile("mma.sync.aligned.m16n8k8.row.col.f32.tf32.tf32.f32 "
                 "{%0,%1,%2,%3}, {%4,%5,%6,%7}, {%8,%9}, {%0,%1,%2,%3};"
                 : "+f"(c[0]), "+f"(c[1]), "+f"(c[2]), "+f"(c[3])
                 : "r"(a[0]), "r"(a[1]), "r"(a[2]), "r"(a[3]), "r"(b0), "r"(b1));
}
__device__ __forceinline__ void ldsm4(u32 r[4], u32 addr) {
    asm volatile("ldmatrix.sync.aligned.m8n8.x4.shared.b16 {%0,%1,%2,%3}, [%4];"
                 : "=r"(r[0]), "=r"(r[1]), "=r"(r[2]), "=r"(r[3]) : "r"(addr));
}
#define BAR_SYNC(id)   asm volatile("bar.sync %0, %1;"   :: "r"(id), "r"(NTHREADS) : "memory")
#define BAR_ARRIVE(id) asm volatile("bar.arrive %0, %1;" :: "r"(id), "r"(NTHREADS) : "memory")

// ---------------- prep: fold linear chain into per-warp register layout ----------------
__global__ void prep_kernel(const float* __restrict__ msg_w, const float* __restrict__ msg_b,
                            const float* __restrict__ w_ih, const float* __restrict__ w_hh,
                            const float* __restrict__ b_ih, const float* __restrict__ b_hh) {
    int t = blockIdx.x * blockDim.x + threadIdx.x;
    if (t < 8*8*6*64) {
        int r    = t & 1;
        int lane = (t >> 1) & 31;
        int slot = (t >> 6) % 6;
        int ks   = (t / (6*64)) % 8;
        int wd   = t / (6*64*8);
        int g = lane >> 2, tig = lane & 3;
        int nbase = (slot >> 1) * 64;           // 0 for R, 64 for Z, 128 for I/HN
        int n = nbase + wd*8 + g;
        int k = ks*8 + tig + r*4;
        float v;
        if ((slot & 1) == 0) {                  // GA chain: msg_w^T * w_ih^T
            float s = 0.f;
            #pragma unroll 8
            for (int f = 0; f < FD; f++)
                s += msg_w[f*FD + k] * w_ih[n*FD + f];
            v = s;
        } else {                                // GH chain: w_hh
            v = w_hh[n*FD + k];
        }
        g_W[t] = tf32r(v);
    }
    if (t < 192) {
        float s = 0.f;
        #pragma unroll 8
        for (int f = 0; f < FD; f++) s += msg_b[f] * w_ih[t*FD + f];
        float bA = s + b_ih[t];
        if (t < 128)      g_bias[t] = bA + b_hh[t];
        else            { g_bias[t] = bA; g_bias[t + 64] = b_hh[t]; }
    }
}

// ---------------- main persistent warp-specialized kernel ----------------
__global__ void __launch_bounds__(NTHREADS, 1)
skeleton_gnn_regw(const float* __restrict__ feats,
                  const float* __restrict__ vis,
                  float* __restrict__ out)
{
    extern __shared__ float sm[];
    const int tid = threadIdx.x;

    if (tid >= 256) {
        // ================= PRODUCER (warps 8..9): one row per thread =================
        const int row = tid - 256;              // 0..63
        int iter = 0;
        for (int t = blockIdx.x; t < NTILES; t += GRID_MAIN, ++iter) {
            const int p = iter & 1;
            if (iter >= 2) BAR_SYNC(3 + p);
            float* As = sm + p*BUF_F;
            float* Ah = As + AH_F;

            int gr = t*TILE_M + row;
            int b = (int)((u32)gr / 33u);
            int j = gr - b*33;
            const float4* fb = (const float4*)feats + (size_t)b * 528;   // 33*16
            const float4* srow = fb + j*16;

            float w0 = __ldg(vis + b*NJ + j);
            float ic = c_invcnt[j];
            int cnt = c_cnt[j];
            int n1 = c_nbr[j][1], n2 = c_nbr[j][2], n3 = c_nbr[j][3];
            float wv1 = 0.f, wv2 = 0.f, wv3 = 0.f;
            if (cnt > 1) wv1 = __ldg(vis + b*NJ + n1);
            if (cnt > 2) wv2 = __ldg(vis + b*NJ + n2);
            if (cnt > 3) wv3 = __ldg(vis + b*NJ + n3);
            const float4* nr1 = fb + n1*16;
            const float4* nr2 = fb + n2*16;
            const float4* nr3 = fb + n3*16;

            float* hp = Ah + row*A_STRIDE;
            float* ap = As + row*A_STRIDE;
            #pragma unroll
            for (int c4 = 0; c4 < 16; c4 += 4) {
                float4 s0 = srow[c4+0], s1 = srow[c4+1], s2 = srow[c4+2], s3 = srow[c4+3];
                *(float4*)(hp + c4*4 + 0)  = tf4(s0);
                *(float4*)(hp + c4*4 + 4)  = tf4(s1);
                *(float4*)(hp + c4*4 + 8)  = tf4(s2);
                *(float4*)(hp + c4*4 + 12) = tf4(s3);
                float a[16];
                a[0]=w0*s0.x; a[1]=w0*s0.y; a[2]=w0*s0.z; a[3]=w0*s0.w;
                a[4]=w0*s1.x; a[5]=w0*s1.y; a[6]=w0*s1.z; a[7]=w0*s1.w;
                a[8]=w0*s2.x; a[9]=w0*s2.y; a[10]=w0*s2.z; a[11]=w0*s2.w;
                a[12]=w0*s3.x; a[13]=w0*s3.y; a[14]=w0*s3.z; a[15]=w0*s3.w;
                if (cnt > 1) {
                    #pragma unroll
                    for (int i = 0; i < 4; i++) {
                        float4 nv = nr1[c4+i];
                        a[i*4+0]+=wv1*nv.x; a[i*4+1]+=wv1*nv.y; a[i*4+2]+=wv1*nv.z; a[i*4+3]+=wv1*nv.w;
                    }
                }
                if (cnt > 2) {
                    #pragma unroll
                    for (int i = 0; i < 4; i++) {
                        float4 nv = nr2[c4+i];
                        a[i*4+0]+=wv2*nv.x; a[i*4+1]+=wv2*nv.y; a[i*4+2]+=wv2*nv.z; a[i*4+3]+=wv2*nv.w;
                    }
                }
                if (cnt > 3) {
                    #pragma unroll
                    for (int i = 0; i < 4; i++) {
                        float4 nv = nr3[c4+i];
                        a[i*4+0]+=wv3*nv.x; a[i*4+1]+=wv3*nv.y; a[i*4+2]+=wv3*nv.z; a[i*4+3]+=wv3*nv.w;
                    }
                }
                #pragma unroll
                for (int i = 0; i < 4; i++) {
                    float4 v = make_float4(a[i*4]*ic, a[i*4+1]*ic, a[i*4+2]*ic, a[i*4+3]*ic);
                    *(float4*)(ap + c4*4 + i*4) = tf4(v);
                }
            }
            __threadfence_block();
            BAR_ARRIVE(1 + p);
        }
    } else {
        // ================= CONSUMER (warps 0..7) =================
        const int wd   = tid >> 5;              // d-slice: cols wd*8 .. wd*8+7
        const int lane = tid & 31;
        const int g    = lane >> 2;
        const int tig  = lane & 3;

        // --- load tile-invariant weight fragments into registers (96 u32) ---
        u32 wr[8][12];
        {
            const float2* gw = (const float2*)g_W;
            #pragma unroll
            for (int ks = 0; ks < 8; ks++)
                #pragma unroll
                for (int slot = 0; slot < 6; slot++) {
                    float2 v = gw[(((wd*8 + ks)*6 + slot)*64 >> 1) + lane];
                    wr[ks][slot*2]   = __float_as_uint(v.x);
                    wr[ks][slot*2+1] = __float_as_uint(v.y);
                }
        }
        // --- biases for this lane's two columns ---
        const int d0 = wd*8 + 2*tig;
        float bR0, bR1, bZ0, bZ1, bI0, bI1, bH0, bH1;
        {
            float2 v;
            v = *(const float2*)(g_bias + d0);        bR0 = v.x; bR1 = v.y;
            v = *(const float2*)(g_bias + 64 + d0);   bZ0 = v.x; bZ1 = v.y;
            v = *(const float2*)(g_bias + 128 + d0);  bI0 = v.x; bI1 = v.y;
            v = *(const float2*)(g_bias + 192 + d0);  bH0 = v.x; bH1 = v.y;
        }

        // ldmatrix per-lane byte offset (within a buffer) for mb=0
        const int mat  = lane >> 3;
        const int arow = (lane & 7) + ((mat & 1) << 3);
        const u32 aoff = (u32)((arow*A_STRIDE + ((mat >> 1) << 2)) * 4);
        const u32 sbase = smem_u32(sm);

        int iter = 0;
        for (int t = blockIdx.x; t < NTILES; t += GRID_MAIN, ++iter) {
            const int p = iter & 1;
            BAR_SYNC(1 + p);
            const u32 abase = sbase + (u32)(p*BUF_F*4) + aoff;

            float accR[4][4], accZ[4][4], accI[4][4], accH[4][4];
            #pragma unroll
            for (int mb = 0; mb < 4; mb++) {
                accR[mb][0]=bR0; accR[mb][1]=bR1; accR[mb][2]=bR0; accR[mb][3]=bR1;
                accZ[mb][0]=bZ0; accZ[mb][1]=bZ1; accZ[mb][2]=bZ0; accZ[mb][3]=bZ1;
                accI[mb][0]=bI0; accI[mb][1]=bI1; accI[mb][2]=bI0; accI[mb][3]=bI1;
                accH[mb][0]=bH0; accH[mb][1]=bH1; accH[mb][2]=bH0; accH[mb][3]=bH1;
            }

            #pragma unroll
            for (int ks = 0; ks < 8; ks++) {
                #pragma unroll
                for (int mb = 0; mb < 4; mb++) {
                    u32 fa[4], fh[4];
                    const u32 ad = abase + (u32)(mb*16*A_STRIDE*4 + ks*32);
                    ldsm4(fa, ad);
                    ldsm4(fh, ad + AH_BYTES);
                    mma8(accR[mb], fa, wr[ks][0],  wr[ks][1]);
                    mma8(accR[mb], fh, wr[ks][2],  wr[ks][3]);
                    mma8(accZ[mb], fa, wr[ks][4],  wr[ks][5]);
                    mma8(accZ[mb], fh, wr[ks][6],  wr[ks][7]);
                    mma8(accI[mb], fa, wr[ks][8],  wr[ks][9]);
                    mma8(accH[mb], fh, wr[ks][10], wr[ks][11]);
                }
            }
            BAR_ARRIVE(3 + p);

            // gates + direct store (h re-read exact from gmem, L2-hot)
            const int gr0 = t * TILE_M;
            #pragma unroll
            for (int mb = 0; mb < 4; mb++) {
                const int r0 = gr0 + mb*16 + g;
                const int r1 = r0 + 8;
                float2 h0 = *(const float2*)(feats + (size_t)r0*FD + d0);
                float2 h1 = *(const float2*)(feats + (size_t)r1*FD + d0);
                float2 o0, o1;
                {
                    float r = sigm(accR[mb][0]), z = sigm(accZ[mb][0]);
                    float n = tanh_ap(accI[mb][0] + r*accH[mb][0]);
                    o0.x = (1.0f - z)*n + z*h0.x;
                }
                {
                    float r = sigm(accR[mb][1]), z = sigm(accZ[mb][1]);
                    float n = tanh_ap(accI[mb][1] + r*accH[mb][1]);
                    o0.y = (1.0f - z)*n + z*h0.y;
                }
                {
                    float r = sigm(accR[mb][2]), z = sigm(accZ[mb][2]);
                    float n = tanh_ap(accI[mb][2] + r*accH[mb][2]);
                    o1.x = (1.0f - z)*n + z*h1.x;
                }
                {
                    float r = sigm(accR[mb][3]), z = sigm(accZ[mb][3]);
                    float n = tanh_ap(accI[mb][3] + r*accH[mb][3]);
                    o1.y = (1.0f - z)*n + z*h1.y;
                }
                *(float2*)(out + (size_t)r0*FD + d0) = o0;
                *(float2*)(out + (size_t)r1*FD + d0) = o1;
            }
        }
    }
}

extern "C" void kernel_launch(void* const* d_in, const int* in_sizes, int n_in,
                              void* d_out, int out_size)
{
    const float* feats = (const float*)d_in[0];
    const float* vis   = (const float*)d_in[1];
    const float* msg_w = (const float*)d_in[2];
    const float* msg_b = (const float*)d_in[3];
    const float* w_ih  = (const float*)d_in[4];
    const float* w_hh  = (const float*)d_in[5];
    const float* b_ih  = (const float*)d_in[6];
    const float* b_hh  = (const float*)d_in[7];
    float* out = (float*)d_out;

    cudaFuncSetAttribute(skeleton_gnn_regw,
                         cudaFuncAttributeMaxDynamicSharedMemorySize, SMEM_BYTES);

    prep_kernel<<<24, 1024>>>(msg_w, msg_b, w_ih, w_hh, b_ih, b_hh);
    skeleton_gnn_regw<<<GRID_MAIN, NTHREADS, SMEM_BYTES>>>(feats, vis, out);
}

// round 8
// speedup vs baseline: 1.5750x; 1.3200x over previous
#include <cuda_runtime.h>
#include <cuda_bf16.h>
#include <cstdint>

typedef unsigned int u32;

#define NJ        33
#define FD        64
#define B_TOTAL   32768
#define M_TOTAL   (B_TOTAL*NJ)        // 1081344
#define TILE_M    64
#define NTILES    (M_TOTAL/TILE_M)    // 16896
#define GRID_MAIN 148
#define NTHREADS  320                 // 8 consumer warps + 2 producer warps

#define RS_BF     72                  // bf16 elems per row (144B; 9*16B -> conflict-free ldsm)
#define ROW_BYTES (RS_BF*2)           // 144
#define AH_BYTES  (TILE_M*ROW_BYTES)  // 9216 per (agg or h) tile
#define BUF_BYTES (2*AH_BYTES)        // 18432 per buffer
#define SMEM_BYTES (2*BUF_BYTES)      // 36864 double-buffered

// ---------------- neighbor tables (self first) ----------------
__constant__ int c_nbr[NJ][4] = {
    {0,0,0,0},{1,0,0,0},{2,0,0,0},{3,0,0,0},{4,0,0,0},{5,0,0,0},{6,0,0,0},
    {7,0,0,0},{8,0,0,0},{9,0,0,0},{10,0,0,0},
    {11,12,23,13},{12,11,24,14},{13,11,15,0},{14,12,16,0},{15,13,0,0},{16,14,0,0},
    {17,0,0,0},{18,0,0,0},{19,0,0,0},{20,0,0,0},{21,0,0,0},{22,0,0,0},
    {23,11,24,25},{24,12,23,26},{25,23,27,0},{26,24,28,0},{27,25,0,0},{28,26,0,0},
    {29,0,0,0},{30,0,0,0},{31,0,0,0},{32,0,0,0}
};
__constant__ int c_cnt[NJ] = {1,1,1,1,1,1,1,1,1,1,1, 4,4,3,3,2,2, 1,1,1,1,1,1,
                              4,4,3,3,2,2, 1,1,1,1};
__constant__ float c_invcnt[NJ] = {1.f,1.f,1.f,1.f,1.f,1.f,1.f,1.f,1.f,1.f,1.f,
                                   0.25f,0.25f,1.f/3.f,1.f/3.f,0.5f,0.5f,
                                   1.f,1.f,1.f,1.f,1.f,1.f,
                                   0.25f,0.25f,1.f/3.f,1.f/3.f,0.5f,0.5f,
                                   1.f,1.f,1.f,1.f};

// register-resident bf16 weight fragments, written by prep kernel.
// u32 index: blk*128 + lane*4 + e, blk = (wd*4 + ks)*3 + q
//   q=0: e0/e1 = R chain GA regs(b0,b1), e2/e3 = R chain GH
//   q=1: Z chain (GA, GH)     q=2: e0/e1 = I chain GA, e2/e3 = HN chain GH
//   n = gatebase(q) + wd*8 + (lane>>2)
//   k0 = ks*16 + (lane&3)*2 + r*8, pair (k0, k0+1) packed lo/hi
__device__ __align__(16) u32 g_W[96*128];       // 12288 u32 = 48KB
__device__ float g_bias[256];                   // R | Z | IN | HN

// ---------------- helpers ----------------
__device__ __forceinline__ u32 smem_u32(const void* p) {
    u32 a;
    asm("{ .reg .u64 t; cvta.to.shared.u64 t, %1; cvt.u32.u64 %0, t; }" : "=r"(a) : "l"(p));
    return a;
}
__device__ __forceinline__ u32 bf2(float lo, float hi) {
    u32 r;
    asm("cvt.rn.bf16x2.f32 %0, %1, %2;" : "=r"(r) : "f"(hi), "f"(lo));
    return r;
}
__device__ __forceinline__ float tanh_ap(float x) {
    float y; asm("tanh.approx.f32 %0, %1;" : "=f"(y) : "f"(x)); return y;
}
__device__ __forceinline__ float sigm(float x) { return 0.5f * tanh_ap(0.5f * x) + 0.5f; }
__device__ __forceinline__ void mma16(float c[4], const u32 a[4], u32 b0, u32 b1) {
    asm volatile("mma.sync.aligned.m16n8k16.row.col.f32.bf16.bf16.f32 "
                 "{%0,%1,%2,%3}, {%4,%5,%6,%7}, {%8,%9}, {%0,%1,%2,%3};"
                 : "+f"(c[0]), "+f"(c[1]), "+f"(c[2]), "+f"(c[3])
                 : "r"(a[0]), "r"(a[1]), "r"(a[2]), "r"(a[3]), "r"(b0), "r"(b1));
}
__device__ __forceinline__ void ldsm4(u32 r[4], u32 addr) {
    asm volatile("ldmatrix.sync.aligned.m8n8.x4.shared.b16 {%0,%1,%2,%3}, [%4];"
                 : "=r"(r[0]), "=r"(r[1]), "=r"(r[2]), "=r"(r[3]) : "r"(addr));
}
#define BAR_SYNC(id)   asm volatile("bar.sync %0, %1;"   :: "r"(id), "r"(NTHREADS) : "memory")
#define BAR_ARRIVE(id) asm volatile("bar.arrive %0, %1;" :: "r"(id), "r"(NTHREADS) : "memory")

// ---------------- prep: fold linear chain into bf16 fragment layout ----------------
__global__ void prep_kernel(const float* __restrict__ msg_w, const float* __restrict__ msg_b,
                            const float* __restrict__ w_ih, const float* __restrict__ w_hh,
                            const float* __restrict__ b_ih, const float* __restrict__ b_hh) {
    int t = blockIdx.x * blockDim.x + threadIdx.x;
    if (t < 96*128) {
        int e    = t & 3;
        int lane = (t >> 2) & 31;
        int blk  = t >> 7;            // 0..95
        int q    = blk % 3;
        int kswd = blk / 3;
        int ks   = kswd & 3;
        int wd   = kswd >> 2;
        int r    = e & 1;
        bool isH = (e >= 2);
        int gatebase = q * 64;        // 0=R, 64=Z, 128=I/HN
        int n  = gatebase + wd*8 + (lane >> 2);
        int k0 = ks*16 + (lane & 3)*2 + r*8;
        float v0, v1;
        if (!isH) {                   // GA chain: msg_w^T fold w_ih
            float s0 = 0.f, s1 = 0.f;
            #pragma unroll 8
            for (int f = 0; f < FD; f++) {
                float wi = w_ih[n*FD + f];
                s0 += msg_w[f*FD + k0]     * wi;
                s1 += msg_w[f*FD + k0 + 1] * wi;
            }
            v0 = s0; v1 = s1;
        } else {                      // GH chain: w_hh
            v0 = w_hh[n*FD + k0];
            v1 = w_hh[n*FD + k0 + 1];
        }
        g_W[t] = bf2(v0, v1);
    }
    if (t < 192) {
        float s = 0.f;
        #pragma unroll 8
        for (int f = 0; f < FD; f++) s += msg_b[f] * w_ih[t*FD + f];
        float bA = s + b_ih[t];
        if (t < 128)      g_bias[t] = bA + b_hh[t];
        else            { g_bias[t] = bA; g_bias[t + 64] = b_hh[t]; }
    }
}

// ---------------- main persistent warp-specialized kernel ----------------
__global__ void __launch_bounds__(NTHREADS, 1)
skeleton_gnn_bf16(const float* __restrict__ feats,
                  const float* __restrict__ vis,
                  float* __restrict__ out)
{
    extern __shared__ char sm[];
    const int tid = threadIdx.x;

    if (tid >= 256) {
        // ================= PRODUCER (warps 8..9): one row per thread =================
        const int row = tid - 256;              // 0..63
        int iter = 0;
        for (int t = blockIdx.x; t < NTILES; t += GRID_MAIN, ++iter) {
            const int p = iter & 1;
            if (iter >= 2) BAR_SYNC(3 + p);
            char* As = sm + p*BUF_BYTES;
            char* Ah = As + AH_BYTES;

            int gr = t*TILE_M + row;
            int b = (int)((u32)gr / 33u);
            int j = gr - b*33;
            const float4* fb = (const float4*)feats + (size_t)b * 528;   // 33*16
            const float4* srow = fb + j*16;

            float w0 = __ldg(vis + b*NJ + j);
            float ic = c_invcnt[j];
            int cnt = c_cnt[j];
            int n1 = c_nbr[j][1], n2 = c_nbr[j][2], n3 = c_nbr[j][3];
            float wv1 = 0.f, wv2 = 0.f, wv3 = 0.f;
            if (cnt > 1) wv1 = __ldg(vis + b*NJ + n1);
            if (cnt > 2) wv2 = __ldg(vis + b*NJ + n2);
            if (cnt > 3) wv3 = __ldg(vis + b*NJ + n3);
            const float4* nr1 = fb + n1*16;
            const float4* nr2 = fb + n2*16;
            const float4* nr3 = fb + n3*16;

            uint4* hp = (uint4*)(Ah + row*ROW_BYTES);
            uint4* ap = (uint4*)(As + row*ROW_BYTES);
            #pragma unroll
            for (int c4 = 0; c4 < 16; c4 += 2) {
                float4 s0 = srow[c4], s1 = srow[c4+1];
                hp[c4 >> 1] = make_uint4(bf2(s0.x, s0.y), bf2(s0.z, s0.w),
                                         bf2(s1.x, s1.y), bf2(s1.z, s1.w));
                float a[8];
                a[0]=w0*s0.x; a[1]=w0*s0.y; a[2]=w0*s0.z; a[3]=w0*s0.w;
                a[4]=w0*s1.x; a[5]=w0*s1.y; a[6]=w0*s1.z; a[7]=w0*s1.w;
                if (cnt > 1) {
                    float4 v0 = nr1[c4], v1 = nr1[c4+1];
                    a[0]+=wv1*v0.x; a[1]+=wv1*v0.y; a[2]+=wv1*v0.z; a[3]+=wv1*v0.w;
                    a[4]+=wv1*v1.x; a[5]+=wv1*v1.y; a[6]+=wv1*v1.z; a[7]+=wv1*v1.w;
                }
                if (cnt > 2) {
                    float4 v0 = nr2[c4], v1 = nr2[c4+1];
                    a[0]+=wv2*v0.x; a[1]+=wv2*v0.y; a[2]+=wv2*v0.z; a[3]+=wv2*v0.w;
                    a[4]+=wv2*v1.x; a[5]+=wv2*v1.y; a[6]+=wv2*v1.z; a[7]+=wv2*v1.w;
                }
                if (cnt > 3) {
                    float4 v0 = nr3[c4], v1 = nr3[c4+1];
                    a[0]+=wv3*v0.x; a[1]+=wv3*v0.y; a[2]+=wv3*v0.z; a[3]+=wv3*v0.w;
                    a[4]+=wv3*v1.x; a[5]+=wv3*v1.y; a[6]+=wv3*v1.z; a[7]+=wv3*v1.w;
                }
                ap[c4 >> 1] = make_uint4(bf2(a[0]*ic, a[1]*ic), bf2(a[2]*ic, a[3]*ic),
                                         bf2(a[4]*ic, a[5]*ic), bf2(a[6]*ic, a[7]*ic));
            }
            __threadfence_block();
            BAR_ARRIVE(1 + p);
        }
    } else {
        // ================= CONSUMER (warps 0..7) =================
        const int wd   = tid >> 5;              // d-slice: cols wd*8 .. wd*8+7
        const int lane = tid & 31;
        const int g    = lane >> 2;
        const int tig  = lane & 3;

        // --- tile-invariant bf16 weight fragments (48 u32/lane) ---
        u32 wr[4][12];
        {
            const uint4* gw4 = (const uint4*)g_W;
            #pragma unroll
            for (int ks = 0; ks < 4; ks++)
                #pragma unroll
                for (int q = 0; q < 3; q++) {
                    uint4 v = gw4[((wd*4 + ks)*3 + q)*32 + lane];
                    wr[ks][q*4+0] = v.x; wr[ks][q*4+1] = v.y;
                    wr[ks][q*4+2] = v.z; wr[ks][q*4+3] = v.w;
                }
        }
        // --- biases for this lane's two columns ---
        const int d0 = wd*8 + 2*tig;
        float bR0, bR1, bZ0, bZ1, bI0, bI1, bH0, bH1;
        {
            float2 v;
            v = *(const float2*)(g_bias + d0);        bR0 = v.x; bR1 = v.y;
            v = *(const float2*)(g_bias + 64 + d0);   bZ0 = v.x; bZ1 = v.y;
            v = *(const float2*)(g_bias + 128 + d0);  bI0 = v.x; bI1 = v.y;
            v = *(const float2*)(g_bias + 192 + d0);  bH0 = v.x; bH1 = v.y;
        }

        // ldmatrix per-lane byte offset within a buffer (mb=0, ks=0)
        const int mat  = lane >> 3;
        const int arow = (lane & 7) + ((mat & 1) << 3);
        const u32 aoff = (u32)(arow*ROW_BYTES + ((mat >> 1) << 4));
        const u32 sbase = smem_u32(sm);

        int iter = 0;
        for (int t = blockIdx.x; t < NTILES; t += GRID_MAIN, ++iter) {
            const int p = iter & 1;
            BAR_SYNC(1 + p);
            const u32 abase = sbase + (u32)(p*BUF_BYTES) + aoff;

            float accR[4][4], accZ[4][4], accI[4][4], accH[4][4];
            #pragma unroll
            for (int mb = 0; mb < 4; mb++) {
                accR[mb][0]=bR0; accR[mb][1]=bR1; accR[mb][2]=bR0; accR[mb][3]=bR1;
                accZ[mb][0]=bZ0; accZ[mb][1]=bZ1; accZ[mb][2]=bZ0; accZ[mb][3]=bZ1;
                accI[mb][0]=bI0; accI[mb][1]=bI1; accI[mb][2]=bI0; accI[mb][3]=bI1;
                accH[mb][0]=bH0; accH[mb][1]=bH1; accH[mb][2]=bH0; accH[mb][3]=bH1;
            }

            #pragma unroll
            for (int ks = 0; ks < 4; ks++) {
                #pragma unroll
                for (int mb = 0; mb < 4; mb++) {
                    u32 fa[4], fh[4];
                    const u32 ad = abase + (u32)(mb*16*ROW_BYTES + ks*32);
                    ldsm4(fa, ad);
                    ldsm4(fh, ad + AH_BYTES);
                    mma16(accR[mb], fa, wr[ks][0],  wr[ks][1]);
                    mma16(accR[mb], fh, wr[ks][2],  wr[ks][3]);
                    mma16(accZ[mb], fa, wr[ks][4],  wr[ks][5]);
                    mma16(accZ[mb], fh, wr[ks][6],  wr[ks][7]);
                    mma16(accI[mb], fa, wr[ks][8],  wr[ks][9]);
                    mma16(accH[mb], fh, wr[ks][10], wr[ks][11]);
                }
            }
            BAR_ARRIVE(3 + p);

            // gates + direct store (h re-read exact fp32 from gmem, L2-hot)
            const int gr0 = t * TILE_M;
            #pragma unroll
            for (int mb = 0; mb < 4; mb++) {
                const int r0 = gr0 + mb*16 + g;
                const int r1 = r0 + 8;
                float2 h0 = *(const float2*)(feats + (size_t)r0*FD + d0);
                float2 h1 = *(const float2*)(feats + (size_t)r1*FD + d0);
                float2 o0, o1;
                {
                    float r = sigm(accR[mb][0]), z = sigm(accZ[mb][0]);
                    float n = tanh_ap(accI[mb][0] + r*accH[mb][0]);
                    o0.x = (1.0f - z)*n + z*h0.x;
                }
                {
                    float r = sigm(accR[mb][1]), z = sigm(accZ[mb][1]);
                    float n = tanh_ap(accI[mb][1] + r*accH[mb][1]);
                    o0.y = (1.0f - z)*n + z*h0.y;
                }
                {
                    float r = sigm(accR[mb][2]), z = sigm(accZ[mb][2]);
                    float n = tanh_ap(accI[mb][2] + r*accH[mb][2]);
                    o1.x = (1.0f - z)*n + z*h1.x;
                }
                {
                    float r = sigm(accR[mb][3]), z = sigm(accZ[mb][3]);
                    float n = tanh_ap(accI[mb][3] + r*accH[mb][3]);
                    o1.y = (1.0f - z)*n + z*h1.y;
                }
                *(float2*)(out + (size_t)r0*FD + d0) = o0;
                *(float2*)(out + (size_t)r1*FD + d0) = o1;
            }
        }
    }
}

extern "C" void kernel_launch(void* const* d_in, const int* in_sizes, int n_in,
                              void* d_out, int out_size)
{
    const float* feats = (const float*)d_in[0];
    const float* vis   = (const float*)d_in[1];
    const float* msg_w = (const float*)d_in[2];
    const float* msg_b = (const float*)d_in[3];
    const float* w_ih  = (const float*)d_in[4];
    const float* w_hh  = (const float*)d_in[5];
    const float* b_ih  = (const float*)d_in[6];
    const float* b_hh  = (const float*)d_in[7];
    float* out = (float*)d_out;

    cudaFuncSetAttribute(skeleton_gnn_bf16,
                         cudaFuncAttributeMaxDynamicSharedMemorySize, SMEM_BYTES);

    prep_kernel<<<24, 1024>>>(msg_w, msg_b, w_ih, w_hh, b_ih, b_hh);
    skeleton_gnn_bf16<<<GRID_MAIN, NTHREADS, SMEM_BYTES>>>(feats, vis, out);
}